// round 4
// baseline (speedup 1.0000x reference)
#include <cuda_runtime.h>
#include <cuda_fp16.h>
#include <cstdint>
#include <cstddef>

// ---------------------------------------------------------------------------
// Problem constants
// ---------------------------------------------------------------------------
#define M_ROWS 512
#define N_OUT  8192
#define K_IN   8192

#define TILE_M 128
#define TILE_N 128
#define TILE_K 64                     // K elements per chunk
#define NCHUNK (K_IN / TILE_K)        // 128

#define A_STAGE_BYTES  (TILE_M * TILE_K * 2)   // 16384 fp16, swizzled
#define R_STAGE_BYTES  (TILE_N * TILE_K * 4)   // 32768 raw int32, linear
#define BF_STAGE_BYTES (TILE_N * TILE_K * 2)   // 16384 fp16, swizzled
#define SMEM_TOTAL (2 * A_STAGE_BYTES + 2 * R_STAGE_BYTES + 2 * BF_STAGE_BYTES) // 131072

// ---------------------------------------------------------------------------
// Scratch (device global: allocation-free rule)
// ---------------------------------------------------------------------------
__device__ __half g_xh[(size_t)M_ROWS * K_IN];  // 8 MB fp16 x

// ---------------------------------------------------------------------------
// Helpers
// ---------------------------------------------------------------------------
__device__ __forceinline__ uint32_t smem_u32(const void* p) {
    uint32_t a;
    asm("{ .reg .u64 t; cvta.to.shared.u64 t, %1; cvt.u32.u64 %0, t; }"
        : "=r"(a) : "l"(p));
    return a;
}

__device__ __forceinline__ uint32_t sw128(uint32_t off) {
    return off ^ ((off >> 3) & 0x70);
}

__device__ __forceinline__ void cp_async16(uint32_t dst, const void* src) {
    asm volatile("cp.async.cg.shared.global [%0], [%1], 16;\n"
                 :: "r"(dst), "l"(src) : "memory");
}
#define CP_COMMIT() asm volatile("cp.async.commit_group;\n" ::: "memory")
#define CP_WAIT0()  asm volatile("cp.async.wait_group 0;\n" ::: "memory")

__device__ __forceinline__ void ldmatrix_x4(uint32_t* r, uint32_t addr) {
    asm volatile("ldmatrix.sync.aligned.m8n8.x4.shared.b16 {%0,%1,%2,%3}, [%4];\n"
                 : "=r"(r[0]), "=r"(r[1]), "=r"(r[2]), "=r"(r[3]) : "r"(addr));
}

__device__ __forceinline__ void lds128i(int* v, uint32_t addr) {
    asm volatile("ld.shared.v4.b32 {%0,%1,%2,%3}, [%4];\n"
                 : "=r"(v[0]), "=r"(v[1]), "=r"(v[2]), "=r"(v[3]) : "r"(addr));
}

__device__ __forceinline__ void sts64(uint32_t addr, uint32_t a, uint32_t b) {
    asm volatile("st.shared.v2.b32 [%0], {%1,%2};\n"
                 :: "r"(addr), "r"(a), "r"(b) : "memory");
}

__device__ __forceinline__ void mma16816(float* c, const uint32_t* a,
                                         const uint32_t* b) {
    asm volatile(
        "mma.sync.aligned.m16n8k16.row.col.f32.f16.f16.f32 "
        "{%0,%1,%2,%3}, {%4,%5,%6,%7}, {%8,%9}, {%0,%1,%2,%3};\n"
        : "+f"(c[0]), "+f"(c[1]), "+f"(c[2]), "+f"(c[3])
        : "r"(a[0]), "r"(a[1]), "r"(a[2]), "r"(a[3]), "r"(b[0]), "r"(b[1]));
}

// ---------------------------------------------------------------------------
// Kernel 1: x fp32 -> fp16
// ---------------------------------------------------------------------------
__global__ void __launch_bounds__(256) cvt_x_kernel(const float* __restrict__ x) {
    size_t t = (size_t)blockIdx.x * 256 + threadIdx.x;
    size_t base = t * 8;
    float4 a = *reinterpret_cast<const float4*>(x + base);
    float4 b = *reinterpret_cast<const float4*>(x + base + 4);
    __align__(16) __half h[8];
    h[0] = __float2half_rn(a.x); h[1] = __float2half_rn(a.y);
    h[2] = __float2half_rn(a.z); h[3] = __float2half_rn(a.w);
    h[4] = __float2half_rn(b.x); h[5] = __float2half_rn(b.y);
    h[6] = __float2half_rn(b.z); h[7] = __float2half_rn(b.w);
    *reinterpret_cast<uint4*>(g_xh + base) = *reinterpret_cast<uint4*>(h);
}

// ---------------------------------------------------------------------------
// Kernel 2: fused dequant + fp16 GEMM (mma.sync)
//   weight_q arrives as int32 (harness widens int8 -> int32)
//   out[m, n] = sum_k x[m,k] * (wq[n,k] * scale[n/128, k/128])
// ---------------------------------------------------------------------------
__global__ void __launch_bounds__(256) gemm_kernel(
    const int* __restrict__ wq, const float* __restrict__ ws,
    float* __restrict__ out) {
    extern __shared__ char smem[];
    uint32_t sb = smem_u32(smem);
    // layout: A0 | A1 | R0 | R1 | B0 | B1
    const uint32_t sbA[2] = {sb, sb + A_STAGE_BYTES};
    const uint32_t sbR[2] = {sb + 2 * A_STAGE_BYTES,
                             sb + 2 * A_STAGE_BYTES + R_STAGE_BYTES};
    const uint32_t sbB[2] = {sb + 2 * A_STAGE_BYTES + 2 * R_STAGE_BYTES,
                             sb + 2 * A_STAGE_BYTES + 2 * R_STAGE_BYTES + BF_STAGE_BYTES};

    int tid = threadIdx.x;
    int lid = tid & 31;
    int wid = tid >> 5;
    int wm = wid >> 1, wn = wid & 1;          // 4x2 warp grid
    int m_warp = wm * 32, n_warp = wn * 64;   // warp tile 32(m) x 64(n)

    int n0 = blockIdx.x * TILE_N;
    int m0 = blockIdx.y * TILE_M;
    int wsrow = (n0 >> 7) * (K_IN / 128);

    const __half* xh = g_xh;

    float acc[2][8][4];
#pragma unroll
    for (int mi = 0; mi < 2; ++mi)
#pragma unroll
        for (int ni = 0; ni < 8; ++ni)
#pragma unroll
            for (int j = 0; j < 4; ++j) acc[mi][ni][j] = 0.f;

    // ---- staging helpers (expanded inline) ----
    // load A chunk -> slot: 4 x 16B per thread, swizzled fp16 tile
#define LOAD_A(slot, chunk) do {                                              \
    int k0h = (chunk) * TILE_K;                                               \
    _Pragma("unroll")                                                         \
    for (int i = 0; i < 4; ++i) {                                             \
        int seg = tid + i * 256;                                              \
        int row = seg >> 3, c = seg & 7;                                      \
        cp_async16(sbA[slot] + sw128((uint32_t)row * 128 + c * 16),           \
                   xh + (size_t)(m0 + row) * K_IN + k0h + c * 8);             \
    }                                                                         \
} while (0)

    // load raw int32 W chunk -> slot: 8 x 16B per thread, linear layout
    //   raw byte b: n = b/256, int = (b%256)/4
#define LOAD_R(slot, chunk) do {                                              \
    int k0i = (chunk) * TILE_K;                                               \
    _Pragma("unroll")                                                         \
    for (int j = 0; j < 8; ++j) {                                             \
        int seg = tid + j * 256;                                              \
        int n = seg >> 4, u = seg & 15;                                       \
        cp_async16(sbR[slot] + (uint32_t)seg * 16,                            \
                   wq + (size_t)(n0 + n) * K_IN + k0i + u * 4);               \
    }                                                                         \
} while (0)

    // convert raw int32 slot -> swizzled fp16 B slot with scale s
#define CONVERT(slot, s) do {                                                 \
    _Pragma("unroll")                                                         \
    for (int i = 0; i < 8; ++i) {                                             \
        int v[4];                                                             \
        lds128i(v, sbR[slot] + (uint32_t)tid * 16 + i * 4096);                \
        int n = (tid >> 4) + i * 16;                                          \
        int u = tid & 15;                                                     \
        __half2 p0 = __floats2half2_rn((s) * (float)v[0], (s) * (float)v[1]); \
        __half2 p1 = __floats2half2_rn((s) * (float)v[2], (s) * (float)v[3]); \
        sts64(sbB[slot] + sw128((uint32_t)n * 128 + u * 8),                   \
              *reinterpret_cast<uint32_t*>(&p0),                              \
              *reinterpret_cast<uint32_t*>(&p1));                             \
    }                                                                         \
} while (0)

    // ---- prologue ----
    LOAD_A(0, 0);
    LOAD_R(0, 0);
    LOAD_R(1, 1);
    CP_COMMIT();
    CP_WAIT0();
    __syncthreads();
    {
        float s0 = ws[wsrow];
        CONVERT(0, s0);
    }
    __syncthreads();

    // ---- main loop ----
    for (int it = 0; it < NCHUNK; ++it) {
        int cur = it & 1, nxt = cur ^ 1;

        if (it + 2 < NCHUNK) LOAD_R(cur, it + 2);
        if (it + 1 < NCHUNK) LOAD_A(nxt, it + 1);
        CP_COMMIT();

        if (it + 1 < NCHUNK) {
            float s = ws[wsrow + ((it + 1) >> 1)];
            CONVERT(nxt, s);
        }

        // compute chunk `it` from stage cur
#pragma unroll
        for (int ks = 0; ks < 4; ++ks) {
            uint32_t af[2][4];
#pragma unroll
            for (int mi = 0; mi < 2; ++mi) {
                uint32_t off = (uint32_t)(m_warp + mi * 16 + (lid & 15)) * 128
                             + ks * 32 + ((lid >> 4) << 4);
                ldmatrix_x4(af[mi], sbA[cur] + sw128(off));
            }
            uint32_t bf[8][2];
#pragma unroll
            for (int nt = 0; nt < 4; ++nt) {
                uint32_t r[4];
                uint32_t off = (uint32_t)(n_warp + nt * 16 + (lid & 7)
                                          + ((lid >> 4) << 3)) * 128
                             + ks * 32 + (((lid >> 3) & 1) << 4);
                ldmatrix_x4(r, sbB[cur] + sw128(off));
                bf[2 * nt][0] = r[0]; bf[2 * nt][1] = r[1];
                bf[2 * nt + 1][0] = r[2]; bf[2 * nt + 1][1] = r[3];
            }
#pragma unroll
            for (int mi = 0; mi < 2; ++mi)
#pragma unroll
                for (int ni = 0; ni < 8; ++ni)
                    mma16816(acc[mi][ni], af[mi], bf[ni]);
        }

        CP_WAIT0();
        __syncthreads();
    }

    // ---- epilogue ----
#pragma unroll
    for (int mi = 0; mi < 2; ++mi) {
#pragma unroll
        for (int ni = 0; ni < 8; ++ni) {
            int row = m0 + m_warp + mi * 16 + (lid >> 2);
            int col = n0 + n_warp + ni * 8 + ((lid & 3) << 1);
            float2 v0 = make_float2(acc[mi][ni][0], acc[mi][ni][1]);
            float2 v1 = make_float2(acc[mi][ni][2], acc[mi][ni][3]);
            *reinterpret_cast<float2*>(out + (size_t)row * N_OUT + col) = v0;
            *reinterpret_cast<float2*>(out + (size_t)(row + 8) * N_OUT + col) = v1;
        }
    }
}

// ---------------------------------------------------------------------------
// Launch
// ---------------------------------------------------------------------------
extern "C" void kernel_launch(void* const* d_in, const int* in_sizes, int n_in,
                              void* d_out, int out_size) {
    const float* x  = (const float*)d_in[0];
    const int*   wq = (const int*)d_in[1];     // int8 widened to int32 by harness
    const float* ws = (const float*)d_in[2];
    float* out = (float*)d_out;

    cvt_x_kernel<<<2048, 256>>>(x);

    cudaFuncSetAttribute(gemm_kernel,
                         cudaFuncAttributeMaxDynamicSharedMemorySize, SMEM_TOTAL);
    dim3 grid(N_OUT / TILE_N, M_ROWS / TILE_M);  // (64, 4) = 256 CTAs
    gemm_kernel<<<grid, 256, SMEM_TOTAL>>>(wq, ws, out);
}

// round 5
// speedup vs baseline: 1.5535x; 1.5535x over previous
#include <cuda_runtime.h>
#include <cuda_fp16.h>
#include <cstdint>
#include <cstddef>

// ---------------------------------------------------------------------------
// Problem constants
// ---------------------------------------------------------------------------
#define M_ROWS 512
#define N_OUT  8192
#define K_IN   8192

#define TILE_M 128
#define TILE_N 128
#define TILE_K 64                     // K elements per stage
#define NCHUNK (K_IN / TILE_K)        // 128
#define STAGES 3

#define A_STAGE_BYTES (TILE_M * TILE_K * 2)   // 16384 fp16, swizzled
#define B_STAGE_BYTES (TILE_N * TILE_K * 2)   // 16384 fp16, swizzled
#define SMEM_TOTAL (STAGES * (A_STAGE_BYTES + B_STAGE_BYTES))   // 98304

// ---------------------------------------------------------------------------
// Scratch (device globals: allocation-free rule)
// ---------------------------------------------------------------------------
__device__ __half g_xh[(size_t)M_ROWS * K_IN];   // 8 MB fp16 x
__device__ __half g_wh[(size_t)N_OUT * K_IN];    // 128 MB fp16 dequantized W

// ---------------------------------------------------------------------------
// Helpers
// ---------------------------------------------------------------------------
__device__ __forceinline__ uint32_t smem_u32(const void* p) {
    uint32_t a;
    asm("{ .reg .u64 t; cvta.to.shared.u64 t, %1; cvt.u32.u64 %0, t; }"
        : "=r"(a) : "l"(p));
    return a;
}

__device__ __forceinline__ uint32_t sw128(uint32_t off) {
    return off ^ ((off >> 3) & 0x70);
}

__device__ __forceinline__ void cp_async16(uint32_t dst, const void* src) {
    asm volatile("cp.async.cg.shared.global [%0], [%1], 16;\n"
                 :: "r"(dst), "l"(src) : "memory");
}
#define CP_COMMIT() asm volatile("cp.async.commit_group;\n" ::: "memory")
#define CP_WAIT1()  asm volatile("cp.async.wait_group 1;\n" ::: "memory")

__device__ __forceinline__ void ldmatrix_x4(uint32_t* r, uint32_t addr) {
    asm volatile("ldmatrix.sync.aligned.m8n8.x4.shared.b16 {%0,%1,%2,%3}, [%4];\n"
                 : "=r"(r[0]), "=r"(r[1]), "=r"(r[2]), "=r"(r[3]) : "r"(addr));
}

__device__ __forceinline__ void mma16816(float* c, const uint32_t* a,
                                         const uint32_t* b) {
    asm volatile(
        "mma.sync.aligned.m16n8k16.row.col.f32.f16.f16.f32 "
        "{%0,%1,%2,%3}, {%4,%5,%6,%7}, {%8,%9}, {%0,%1,%2,%3};\n"
        : "+f"(c[0]), "+f"(c[1]), "+f"(c[2]), "+f"(c[3])
        : "r"(a[0]), "r"(a[1]), "r"(a[2]), "r"(a[3]), "r"(b[0]), "r"(b[1]));
}

// ---------------------------------------------------------------------------
// Kernel 1: x fp32 -> fp16
// ---------------------------------------------------------------------------
__global__ void __launch_bounds__(256) cvt_x_kernel(const float* __restrict__ x) {
    size_t t = (size_t)blockIdx.x * 256 + threadIdx.x;
    size_t base = t * 8;
    float4 a = *reinterpret_cast<const float4*>(x + base);
    float4 b = *reinterpret_cast<const float4*>(x + base + 4);
    __align__(16) __half h[8];
    h[0] = __float2half_rn(a.x); h[1] = __float2half_rn(a.y);
    h[2] = __float2half_rn(a.z); h[3] = __float2half_rn(a.w);
    h[4] = __float2half_rn(b.x); h[5] = __float2half_rn(b.y);
    h[6] = __float2half_rn(b.z); h[7] = __float2half_rn(b.w);
    *reinterpret_cast<uint4*>(g_xh + base) = *reinterpret_cast<uint4*>(h);
}

// ---------------------------------------------------------------------------
// Kernel 2: dequant W (int32-widened int8 * block scale) -> fp16
// ---------------------------------------------------------------------------
__global__ void __launch_bounds__(256) dequant_w_kernel(
    const int* __restrict__ wq, const float* __restrict__ ws) {
    size_t t = (size_t)blockIdx.x * 256 + threadIdx.x;
    size_t base = t * 8;
    int o = (int)(base >> 13);           // out feature
    int i = (int)(base & (K_IN - 1));    // in feature
    float s = ws[(o >> 7) * (K_IN / 128) + (i >> 7)];
    int4 a = *reinterpret_cast<const int4*>(wq + base);
    int4 b = *reinterpret_cast<const int4*>(wq + base + 4);
    __align__(16) __half h[8];
    h[0] = __float2half_rn(s * (float)a.x);
    h[1] = __float2half_rn(s * (float)a.y);
    h[2] = __float2half_rn(s * (float)a.z);
    h[3] = __float2half_rn(s * (float)a.w);
    h[4] = __float2half_rn(s * (float)b.x);
    h[5] = __float2half_rn(s * (float)b.y);
    h[6] = __float2half_rn(s * (float)b.z);
    h[7] = __float2half_rn(s * (float)b.w);
    *reinterpret_cast<uint4*>(g_wh + base) = *reinterpret_cast<uint4*>(h);
}

// ---------------------------------------------------------------------------
// Kernel 3: fp16 GEMM (mma.sync), 3-stage cp.async pipeline, 2 CTAs/SM
// ---------------------------------------------------------------------------
__global__ void __launch_bounds__(256, 2) gemm_kernel(float* __restrict__ out) {
    extern __shared__ char smem[];
    uint32_t sb = smem_u32(smem);
    // layout per stage: A (16KB) | B (16KB); stages contiguous
    int tid = threadIdx.x;
    int lid = tid & 31;
    int wid = tid >> 5;
    int wm = wid >> 1, wn = wid & 1;          // 4x2 warp grid
    int m_warp = wm * 32, n_warp = wn * 64;   // warp tile 32(m) x 64(n)

    int n0 = blockIdx.x * TILE_N;
    int m0 = blockIdx.y * TILE_M;

    const __half* xh = g_xh;
    const __half* wh = g_wh;

    float acc[2][8][4];
#pragma unroll
    for (int mi = 0; mi < 2; ++mi)
#pragma unroll
        for (int ni = 0; ni < 8; ++ni)
#pragma unroll
            for (int j = 0; j < 4; ++j) acc[mi][ni][j] = 0.f;

    // A/B load: 4 x 16B segments per thread each, swizzled fp16 tiles
#define LOAD_STAGE(slot, chunk) do {                                          \
    int k0h = (chunk) * TILE_K;                                               \
    uint32_t ab = sb + (uint32_t)(slot) * (A_STAGE_BYTES + B_STAGE_BYTES);    \
    uint32_t bb = ab + A_STAGE_BYTES;                                         \
    _Pragma("unroll")                                                         \
    for (int i = 0; i < 4; ++i) {                                             \
        int seg = tid + i * 256;                                              \
        int row = seg >> 3, c = seg & 7;                                      \
        cp_async16(ab + sw128((uint32_t)row * 128 + c * 16),                  \
                   xh + (size_t)(m0 + row) * K_IN + k0h + c * 8);             \
        cp_async16(bb + sw128((uint32_t)row * 128 + c * 16),                  \
                   wh + (size_t)(n0 + row) * K_IN + k0h + c * 8);             \
    }                                                                         \
} while (0)

    // ---- prologue: stages 0,1 in flight ----
    LOAD_STAGE(0, 0);
    CP_COMMIT();
    LOAD_STAGE(1, 1);
    CP_COMMIT();
    CP_WAIT1();              // stage 0 landed
    __syncthreads();

    // ---- main loop ----
    int cur = 0, nxt2 = 2;
#pragma unroll 1
    for (int it = 0; it < NCHUNK; ++it) {
        if (it + 2 < NCHUNK) LOAD_STAGE(nxt2, it + 2);
        CP_COMMIT();

        uint32_t aBase = sb + (uint32_t)cur * (A_STAGE_BYTES + B_STAGE_BYTES);
        uint32_t bBase = aBase + A_STAGE_BYTES;

#pragma unroll
        for (int ks = 0; ks < 4; ++ks) {
            uint32_t af[2][4];
#pragma unroll
            for (int mi = 0; mi < 2; ++mi) {
                uint32_t off = (uint32_t)(m_warp + mi * 16 + (lid & 15)) * 128
                             + ks * 32 + ((lid >> 4) << 4);
                ldmatrix_x4(af[mi], aBase + sw128(off));
            }
            uint32_t bf[8][2];
#pragma unroll
            for (int nt = 0; nt < 4; ++nt) {
                uint32_t r[4];
                uint32_t off = (uint32_t)(n_warp + nt * 16 + (lid & 7)
                                          + ((lid >> 4) << 3)) * 128
                             + ks * 32 + (((lid >> 3) & 1) << 4);
                ldmatrix_x4(r, bBase + sw128(off));
                bf[2 * nt][0] = r[0]; bf[2 * nt][1] = r[1];
                bf[2 * nt + 1][0] = r[2]; bf[2 * nt + 1][1] = r[3];
            }
#pragma unroll
            for (int mi = 0; mi < 2; ++mi)
#pragma unroll
                for (int ni = 0; ni < 8; ++ni)
                    mma16816(acc[mi][ni], af[mi], bf[ni]);
        }

        CP_WAIT1();          // next stage landed
        __syncthreads();

        cur = (cur == STAGES - 1) ? 0 : cur + 1;
        nxt2 = (nxt2 == STAGES - 1) ? 0 : nxt2 + 1;
    }

    // ---- epilogue ----
#pragma unroll
    for (int mi = 0; mi < 2; ++mi) {
#pragma unroll
        for (int ni = 0; ni < 8; ++ni) {
            int row = m0 + m_warp + mi * 16 + (lid >> 2);
            int col = n0 + n_warp + ni * 8 + ((lid & 3) << 1);
            float2 v0 = make_float2(acc[mi][ni][0], acc[mi][ni][1]);
            float2 v1 = make_float2(acc[mi][ni][2], acc[mi][ni][3]);
            *reinterpret_cast<float2*>(out + (size_t)row * N_OUT + col) = v0;
            *reinterpret_cast<float2*>(out + (size_t)(row + 8) * N_OUT + col) = v1;
        }
    }
}

// ---------------------------------------------------------------------------
// Launch
// ---------------------------------------------------------------------------
extern "C" void kernel_launch(void* const* d_in, const int* in_sizes, int n_in,
                              void* d_out, int out_size) {
    const float* x  = (const float*)d_in[0];
    const int*   wq = (const int*)d_in[1];     // int8 widened to int32 by harness
    const float* ws = (const float*)d_in[2];
    float* out = (float*)d_out;

    cvt_x_kernel<<<2048, 256>>>(x);
    dequant_w_kernel<<<32768, 256>>>(wq, ws);

    cudaFuncSetAttribute(gemm_kernel,
                         cudaFuncAttributeMaxDynamicSharedMemorySize, SMEM_TOTAL);
    dim3 grid(N_OUT / TILE_N, M_ROWS / TILE_M);  // (64, 4) = 256 CTAs
    gemm_kernel<<<grid, 256, SMEM_TOTAL>>>(out);
}